// round 1
// baseline (speedup 1.0000x reference)
#include <cuda_runtime.h>
#include <math.h>

// Problem constants (fixed by reference)
#define DD      2048
#define NB      8        // completed blocks
#define BB      2
#define TT      2048
#define NTOK    (BB * TT)        // 4096 tokens
#define THREADS 256
#define F4_PER_ROW (DD / 4)      // 512 float4 per row
// each thread handles 2 float4 per row: indices tid and tid+256

__device__ __forceinline__ float dot4(float4 a, float4 b) {
    return a.x * b.x + a.y * b.y + a.z * b.z + a.w * b.w;
}
__device__ __forceinline__ float4 fma4(float4 a, float s, float4 acc) {
    acc.x += a.x * s; acc.y += a.y * s; acc.z += a.z * s; acc.w += a.w * s;
    return acc;
}

__global__ __launch_bounds__(THREADS, 1)
void reloop_fused_kernel(const float* __restrict__ cb,   // [NB, BB, TT, DD]
                         const float* __restrict__ pb,   // [BB, TT, DD]
                         const float* __restrict__ wq,   // [DD]
                         const float* __restrict__ knw,  // [DD]
                         float* __restrict__ out)        // hidden | entropy | weights
{
    const int bt   = blockIdx.x;          // token index = b*TT + t
    const int tid  = threadIdx.x;
    const int lane = tid & 31;
    const int warp = tid >> 5;

    const float EPS       = 1e-6f;
    const float INV_SCALE = 0.02209708691207961f;  // 1/sqrt(2048)

    // ---- effective query (elementwise w_query * key_norm_weight), this thread's 8 elems
    float4 qa, qb;
    {
        float4 w0 = reinterpret_cast<const float4*>(wq)[tid];
        float4 w1 = reinterpret_cast<const float4*>(wq)[tid + THREADS];
        float4 k0 = reinterpret_cast<const float4*>(knw)[tid];
        float4 k1 = reinterpret_cast<const float4*>(knw)[tid + THREADS];
        qa = make_float4(w0.x * k0.x, w0.y * k0.y, w0.z * k0.z, w0.w * k0.w);
        qb = make_float4(w1.x * k1.x, w1.y * k1.y, w1.z * k1.z, w1.w * k1.w);
    }

    // ---- load all 9 rows into registers; accumulate sumsq + dot per row
    float4 rows[9][2];
    float  ss[9], dp[9];

    #pragma unroll
    for (int n = 0; n < 9; n++) {
        const float* rowp = (n < NB)
            ? (cb + ((size_t)n * NTOK + (size_t)bt) * DD)
            : (pb + (size_t)bt * DD);
        const float4* r4 = reinterpret_cast<const float4*>(rowp);
        float4 x0 = r4[tid];
        float4 x1 = r4[tid + THREADS];
        rows[n][0] = x0;
        rows[n][1] = x1;
        ss[n] = dot4(x0, x0) + dot4(x1, x1);
        dp[n] = dot4(qa, x0) + dot4(qb, x1);
    }

    // ---- block reduction of 18 values (9 sumsq + 9 dot)
    #pragma unroll
    for (int n = 0; n < 9; n++) {
        #pragma unroll
        for (int o = 16; o > 0; o >>= 1) {
            ss[n] += __shfl_xor_sync(0xFFFFFFFFu, ss[n], o);
            dp[n] += __shfl_xor_sync(0xFFFFFFFFu, dp[n], o);
        }
    }
    __shared__ float red[8][18];
    if (lane == 0) {
        #pragma unroll
        for (int n = 0; n < 9; n++) {
            red[warp][n]     = ss[n];
            red[warp][9 + n] = dp[n];
        }
    }
    __syncthreads();
    float ssT[9], dpT[9];
    #pragma unroll
    for (int n = 0; n < 9; n++) { ssT[n] = 0.0f; dpT[n] = 0.0f; }
    #pragma unroll
    for (int w = 0; w < 8; w++) {
        #pragma unroll
        for (int n = 0; n < 9; n++) {
            ssT[n] += red[w][n];
            dpT[n] += red[w][9 + n];
        }
    }

    // ---- scores: (q . x) * inv_rms / SCALE
    float sc[9];
    #pragma unroll
    for (int n = 0; n < 9; n++) {
        float mean = ssT[n] * (1.0f / (float)DD);
        sc[n] = dpT[n] * rsqrtf(mean + EPS) * INV_SCALE;
    }

    // ---- phase 1 softmax over the 8 completed blocks
    float m1 = sc[0];
    #pragma unroll
    for (int n = 1; n < NB; n++) m1 = fmaxf(m1, sc[n]);
    float e[NB], lse = 0.0f;
    #pragma unroll
    for (int n = 0; n < NB; n++) { e[n] = __expf(sc[n] - m1); lse += e[n]; }

    // entropy of phase-1 distribution
    float loglse = logf(lse);
    float ent1 = 0.0f;
    #pragma unroll
    for (int n = 0; n < NB; n++) {
        float p  = e[n] / lse;
        float lp = (sc[n] - m1) - loglse;
        ent1 -= p * lp;
    }

    // ---- phase 2: online-softmax merge with partial block
    float sp    = sc[NB];
    float mm    = fmaxf(m1, sp);
    float c1    = __expf(m1 - mm);
    float cp    = __expf(sp - mm);
    float denom = c1 * lse + cp;
    float pw1   = c1 * lse / denom;   // phase1_weight
    float pw2   = cp / denom;         // partial_weight

    // ---- hidden = routed * pw1 + partial * pw2  (routed uses UNNORMALIZED exp)
    float4 h0 = make_float4(0.f, 0.f, 0.f, 0.f);
    float4 h1 = make_float4(0.f, 0.f, 0.f, 0.f);
    #pragma unroll
    for (int n = 0; n < NB; n++) {
        h0 = fma4(rows[n][0], e[n], h0);
        h1 = fma4(rows[n][1], e[n], h1);
    }
    h0.x = h0.x * pw1 + rows[NB][0].x * pw2;
    h0.y = h0.y * pw1 + rows[NB][0].y * pw2;
    h0.z = h0.z * pw1 + rows[NB][0].z * pw2;
    h0.w = h0.w * pw1 + rows[NB][0].w * pw2;
    h1.x = h1.x * pw1 + rows[NB][1].x * pw2;
    h1.y = h1.y * pw1 + rows[NB][1].y * pw2;
    h1.z = h1.z * pw1 + rows[NB][1].z * pw2;
    h1.w = h1.w * pw1 + rows[NB][1].w * pw2;

    float4* o4 = reinterpret_cast<float4*>(out + (size_t)bt * DD);
    o4[tid]           = h0;
    o4[tid + THREADS] = h1;

    // ---- scalars: entropy + 9 weights
    float* ent_out = out + (size_t)NTOK * DD;
    float* w_out   = ent_out + NTOK;

    if (tid == 0) {
        float w1c = fmaxf(pw1, 1e-8f);
        float w2c = fmaxf(pw2, 1e-8f);
        ent_out[bt] = w1c * ent1 - w1c * logf(w1c) - w2c * logf(w2c);
    }
    if (tid < NB) {
        w_out[(size_t)bt * 9 + tid] = (e[tid] / lse) * pw1;
    }
    if (tid == NB) {
        w_out[(size_t)bt * 9 + NB] = pw2;
    }
}

extern "C" void kernel_launch(void* const* d_in, const int* in_sizes, int n_in,
                              void* d_out, int out_size) {
    const float* cb  = (const float*)d_in[0];   // completed_blocks [8,2,2048,2048]
    const float* pb  = (const float*)d_in[1];   // partial_block    [2,2048,2048]
    const float* wq  = (const float*)d_in[2];   // w_query          [2048]
    const float* knw = (const float*)d_in[3];   // key_norm_weight  [2048]
    float* out = (float*)d_out;

    reloop_fused_kernel<<<NTOK, THREADS>>>(cb, pb, wq, knw, out);
}

// round 4
// speedup vs baseline: 1.1469x; 1.1469x over previous
#include <cuda_runtime.h>
#include <math.h>

#define DD      2048
#define NB      8
#define NTOK    4096            // B*T = 2*2048
#define THREADS 256
#define NROWS   9               // 8 completed + 1 partial
#define SMEM_BYTES   (NROWS * DD * 4 + 8 * 18 * 4)  // 73728 + 576 = 74304

__device__ __forceinline__ float dot4(float4 a, float4 b) {
    return a.x * b.x + a.y * b.y + a.z * b.z + a.w * b.w;
}
__device__ __forceinline__ float4 fma4(float4 a, float s, float4 acc) {
    acc.x += a.x * s; acc.y += a.y * s; acc.z += a.z * s; acc.w += a.w * s;
    return acc;
}

__global__ __launch_bounds__(THREADS, 3)
void reloop_fused_kernel(const float* __restrict__ cb,   // [8, 4096, 2048]
                         const float* __restrict__ pb,   // [4096, 2048]
                         const float* __restrict__ wq,   // [2048]
                         const float* __restrict__ knw,  // [2048]
                         float* __restrict__ out)
{
    extern __shared__ float smem[];                   // row data | reduction scratch
    float4* s4  = reinterpret_cast<float4*>(smem);
    float*  red = smem + NROWS * DD;                  // 8 warps x 18 floats

    const int bt   = blockIdx.x;
    const int tid  = threadIdx.x;
    const int lane = tid & 31;
    const int warp = tid >> 5;

    const float EPS       = 1e-6f;
    const float INV_SCALE = 0.02209708691207961f;     // 1/sqrt(2048)

    // effective query: this thread's 8 elems
    float4 qa, qb;
    {
        float4 w0 = reinterpret_cast<const float4*>(wq)[tid];
        float4 w1 = reinterpret_cast<const float4*>(wq)[tid + THREADS];
        float4 k0 = reinterpret_cast<const float4*>(knw)[tid];
        float4 k1 = reinterpret_cast<const float4*>(knw)[tid + THREADS];
        qa = make_float4(w0.x * k0.x, w0.y * k0.y, w0.z * k0.z, w0.w * k0.w);
        qb = make_float4(w1.x * k1.x, w1.y * k1.y, w1.z * k1.z, w1.w * k1.w);
    }

    // ---- pass 1: stream 9 rows HBM -> (stats in flight) -> smem
    float ss[NROWS], dp[NROWS];
    #pragma unroll
    for (int n = 0; n < NROWS; n++) {
        const float* rowp = (n < NB)
            ? (cb + ((size_t)n * NTOK + (size_t)bt) * DD)
            : (pb + (size_t)bt * DD);
        const float4* r4 = reinterpret_cast<const float4*>(rowp);
        float4 x0 = r4[tid];
        float4 x1 = r4[tid + THREADS];
        ss[n] = dot4(x0, x0) + dot4(x1, x1);
        dp[n] = dot4(qa, x0) + dot4(qb, x1);
        s4[n * (DD / 4) + tid]           = x0;
        s4[n * (DD / 4) + THREADS + tid] = x1;
    }

    // ---- block reduction: 9 sumsq + 9 dot
    #pragma unroll
    for (int n = 0; n < NROWS; n++) {
        #pragma unroll
        for (int o = 16; o > 0; o >>= 1) {
            ss[n] += __shfl_xor_sync(0xFFFFFFFFu, ss[n], o);
            dp[n] += __shfl_xor_sync(0xFFFFFFFFu, dp[n], o);
        }
    }
    if (lane == 0) {
        #pragma unroll
        for (int n = 0; n < NROWS; n++) {
            red[warp * 18 + n]     = ss[n];
            red[warp * 18 + 9 + n] = dp[n];
        }
    }
    __syncthreads();

    float sc[NROWS];
    #pragma unroll
    for (int n = 0; n < NROWS; n++) {
        float s = 0.0f, d = 0.0f;
        #pragma unroll
        for (int w = 0; w < 8; w++) {
            s += red[w * 18 + n];
            d += red[w * 18 + 9 + n];
        }
        float mean = s * (1.0f / (float)DD);
        sc[n] = d * rsqrtf(mean + EPS) * INV_SCALE;
    }

    // ---- phase 1 softmax over 8 completed blocks
    float m1 = sc[0];
    #pragma unroll
    for (int n = 1; n < NB; n++) m1 = fmaxf(m1, sc[n]);
    float e[NB], lse = 0.0f;
    #pragma unroll
    for (int n = 0; n < NB; n++) { e[n] = __expf(sc[n] - m1); lse += e[n]; }

    float loglse = logf(lse);
    float ent1 = 0.0f;
    #pragma unroll
    for (int n = 0; n < NB; n++) {
        float p  = e[n] / lse;
        float lp = (sc[n] - m1) - loglse;
        ent1 -= p * lp;
    }

    // ---- phase 2: online-softmax merge with partial
    float sp    = sc[NB];
    float mm    = fmaxf(m1, sp);
    float c1    = __expf(m1 - mm);
    float cp    = __expf(sp - mm);
    float denom = c1 * lse + cp;
    float pw1   = c1 * lse / denom;
    float pw2   = cp / denom;

    // ---- pass 2: weighted sum from smem
    float4 h0 = make_float4(0.f, 0.f, 0.f, 0.f);
    float4 h1 = make_float4(0.f, 0.f, 0.f, 0.f);
    #pragma unroll
    for (int n = 0; n < NB; n++) {
        h0 = fma4(s4[n * (DD / 4) + tid],           e[n], h0);
        h1 = fma4(s4[n * (DD / 4) + THREADS + tid], e[n], h1);
    }
    {
        float4 p0 = s4[NB * (DD / 4) + tid];
        float4 p1 = s4[NB * (DD / 4) + THREADS + tid];
        h0.x = h0.x * pw1 + p0.x * pw2;
        h0.y = h0.y * pw1 + p0.y * pw2;
        h0.z = h0.z * pw1 + p0.z * pw2;
        h0.w = h0.w * pw1 + p0.w * pw2;
        h1.x = h1.x * pw1 + p1.x * pw2;
        h1.y = h1.y * pw1 + p1.y * pw2;
        h1.z = h1.z * pw1 + p1.z * pw2;
        h1.w = h1.w * pw1 + p1.w * pw2;
    }

    float4* o4 = reinterpret_cast<float4*>(out + (size_t)bt * DD);
    o4[tid]           = h0;
    o4[tid + THREADS] = h1;

    // ---- scalars
    float* ent_out = out + (size_t)NTOK * DD;
    float* w_out   = ent_out + NTOK;

    if (tid == 0) {
        float w1c = fmaxf(pw1, 1e-8f);
        float w2c = fmaxf(pw2, 1e-8f);
        ent_out[bt] = w1c * ent1 - w1c * logf(w1c) - w2c * logf(w2c);
    }
    if (tid < NB) {
        w_out[(size_t)bt * 9 + tid] = (e[tid] / lse) * pw1;
    }
    if (tid == NB) {
        w_out[(size_t)bt * 9 + NB] = pw2;
    }
}

extern "C" void kernel_launch(void* const* d_in, const int* in_sizes, int n_in,
                              void* d_out, int out_size) {
    const float* cb  = (const float*)d_in[0];
    const float* pb  = (const float*)d_in[1];
    const float* wq  = (const float*)d_in[2];
    const float* knw = (const float*)d_in[3];
    float* out = (float*)d_out;

    cudaFuncSetAttribute(reloop_fused_kernel,
                         cudaFuncAttributeMaxDynamicSharedMemorySize, SMEM_BYTES);
    reloop_fused_kernel<<<NTOK, THREADS, SMEM_BYTES>>>(cb, pb, wq, knw, out);
}

// round 5
// speedup vs baseline: 1.3940x; 1.2154x over previous
#include <cuda_runtime.h>
#include <math.h>
#include <stdint.h>

#define DD        2048
#define NB        8
#define NTOK      4096
#define THREADS   256
#define NROWS     9
#define F4_ROW    (DD / 4)                 // 512 float4 per row
#define ROW_BYTES (DD * 4)                 // 8192
#define TOK_BYTES (NROWS * ROW_BYTES)      // 73728
#define NSTAGE    3

// smem layout (floats): [NSTAGE][NROWS*DD] data | red[2][8*18] | mbar[NSTAGE] (8B each)
#define SMEM_BUF_FLOATS   (NSTAGE * NROWS * DD)       // 55296
#define SMEM_RED_FLOATS   (2 * 8 * 18)                // 288
#define SMEM_MBAR_OFF_B   ((SMEM_BUF_FLOATS + SMEM_RED_FLOATS) * 4)
#define SMEM_BYTES        (SMEM_MBAR_OFF_B + NSTAGE * 8)   // 222,360 B

__device__ __forceinline__ float dot4(float4 a, float4 b) {
    return a.x * b.x + a.y * b.y + a.z * b.z + a.w * b.w;
}
__device__ __forceinline__ float4 fma4(float4 a, float s, float4 acc) {
    acc.x += a.x * s; acc.y += a.y * s; acc.z += a.z * s; acc.w += a.w * s;
    return acc;
}
__device__ __forceinline__ uint32_t s2u(const void* p) {
    uint32_t a;
    asm("{ .reg .u64 t; cvta.to.shared.u64 t, %1; cvt.u32.u64 %0, t; }" : "=r"(a) : "l"(p));
    return a;
}
__device__ __forceinline__ void wait_parity(uint32_t mbar, uint32_t par) {
    asm volatile(
        "{\n\t"
        ".reg .pred P1;\n\t"
        "WAIT_LOOP_%=:\n\t"
        "mbarrier.try_wait.parity.acquire.cta.shared::cta.b64 P1, [%0], %1, 0x989680;\n\t"
        "@P1 bra.uni WAIT_DONE_%=;\n\t"
        "bra.uni WAIT_LOOP_%=;\n\t"
        "WAIT_DONE_%=:\n\t"
        "}"
        :: "r"(mbar), "r"(par) : "memory");
}

// issue one token's 9 rows into stage s (called by one thread)
__device__ __forceinline__ void issue_token(const float* __restrict__ cb,
                                            const float* __restrict__ pb,
                                            int bt, uint32_t smem_base, uint32_t mbar_s, int s)
{
    asm volatile("mbarrier.arrive.expect_tx.shared.b64 _, [%0], %1;"
                 :: "r"(mbar_s), "r"((uint32_t)TOK_BYTES) : "memory");
    uint32_t dst0 = smem_base + (uint32_t)s * (uint32_t)TOK_BYTES;
    #pragma unroll
    for (int n = 0; n < NROWS; n++) {
        const float* src = (n < NB)
            ? (cb + ((size_t)n * NTOK + (size_t)bt) * DD)
            : (pb + (size_t)bt * DD);
        asm volatile(
            "cp.async.bulk.shared::cluster.global.mbarrier::complete_tx::bytes [%0], [%1], %2, [%3];"
            :: "r"(dst0 + (uint32_t)(n * ROW_BYTES)), "l"(src),
               "r"((uint32_t)ROW_BYTES), "r"(mbar_s) : "memory");
    }
}

__global__ __launch_bounds__(THREADS, 1)
void reloop_tma_kernel(const float* __restrict__ cb,   // [8, 4096, 2048]
                       const float* __restrict__ pb,   // [4096, 2048]
                       const float* __restrict__ wq,   // [2048]
                       const float* __restrict__ knw,  // [2048]
                       float* __restrict__ out)
{
    extern __shared__ float smem[];
    float* red_base = smem + SMEM_BUF_FLOATS;      // 2 x 144 floats
    const uint32_t smem_base = s2u(smem);
    const uint32_t mbar0 = smem_base + SMEM_MBAR_OFF_B;

    const int tid  = threadIdx.x;
    const int lane = tid & 31;
    const int warp = tid >> 5;
    const int bid  = blockIdx.x;
    const int G    = gridDim.x;

    const float EPS       = 1e-6f;
    const float INV_SCALE = 0.02209708691207961f;   // 1/sqrt(2048)

    if (tid == 0) {
        #pragma unroll
        for (int s = 0; s < NSTAGE; s++)
            asm volatile("mbarrier.init.shared.b64 [%0], 1;" :: "r"(mbar0 + s * 8) : "memory");
        asm volatile("fence.proxy.async.shared::cta;" ::: "memory");
    }
    __syncthreads();

    // effective query (this thread's 8 elems)
    float4 qa, qb;
    {
        float4 w0 = reinterpret_cast<const float4*>(wq)[tid];
        float4 w1 = reinterpret_cast<const float4*>(wq)[tid + THREADS];
        float4 k0 = reinterpret_cast<const float4*>(knw)[tid];
        float4 k1 = reinterpret_cast<const float4*>(knw)[tid + THREADS];
        qa = make_float4(w0.x * k0.x, w0.y * k0.y, w0.z * k0.z, w0.w * k0.w);
        qb = make_float4(w1.x * k1.x, w1.y * k1.y, w1.z * k1.z, w1.w * k1.w);
    }

    const int cnt = (NTOK - bid + G - 1) / G;      // tokens: bid + j*G

    // prologue: prefetch up to NSTAGE tokens
    if (tid == 0) {
        int pre = cnt < NSTAGE ? cnt : NSTAGE;
        for (int j = 0; j < pre; j++)
            issue_token(cb, pb, bid + j * G, smem_base, mbar0 + j * 8, j);
    }

    float* ent_out = out + (size_t)NTOK * DD;
    float* w_out   = ent_out + NTOK;

    int s = 0;
    uint32_t par = 0;
    for (int j = 0; j < cnt; j++) {
        const int bt = bid + j * G;
        wait_parity(mbar0 + s * 8, par);

        // ---- rows smem -> regs, stats in flight
        const float4* b4 = reinterpret_cast<const float4*>(smem + (size_t)s * NROWS * DD);
        float4 x[NROWS][2];
        float ss[NROWS], dp[NROWS];
        #pragma unroll
        for (int n = 0; n < NROWS; n++) {
            x[n][0] = b4[n * F4_ROW + tid];
            x[n][1] = b4[n * F4_ROW + THREADS + tid];
            ss[n] = dot4(x[n][0], x[n][0]) + dot4(x[n][1], x[n][1]);
            dp[n] = dot4(qa, x[n][0]) + dot4(qb, x[n][1]);
        }

        // ---- warp reduction (consumes all x via ss/dp -> LDS complete before barrier)
        #pragma unroll
        for (int n = 0; n < NROWS; n++) {
            #pragma unroll
            for (int o = 16; o > 0; o >>= 1) {
                ss[n] += __shfl_xor_sync(0xFFFFFFFFu, ss[n], o);
                dp[n] += __shfl_xor_sync(0xFFFFFFFFu, dp[n], o);
            }
        }
        float* red = red_base + (j & 1) * 144;
        if (lane == 0) {
            #pragma unroll
            for (int n = 0; n < NROWS; n++) {
                red[warp * 18 + n]     = ss[n];
                red[warp * 18 + 9 + n] = dp[n];
            }
        }
        __syncthreads();

        // stage s is fully consumed (rows in regs) -> refill it now, async
        if (tid == 0 && j + NSTAGE < cnt)
            issue_token(cb, pb, bid + (j + NSTAGE) * G, smem_base, mbar0 + s * 8, s);

        // ---- combine partials, scores
        float sc[NROWS];
        #pragma unroll
        for (int n = 0; n < NROWS; n++) {
            float sv = 0.0f, dv = 0.0f;
            #pragma unroll
            for (int w = 0; w < 8; w++) {
                sv += red[w * 18 + n];
                dv += red[w * 18 + 9 + n];
            }
            float mean = sv * (1.0f / (float)DD);
            sc[n] = dv * rsqrtf(mean + EPS) * INV_SCALE;
        }

        // ---- phase 1 softmax (8 completed)
        float m1 = sc[0];
        #pragma unroll
        for (int n = 1; n < NB; n++) m1 = fmaxf(m1, sc[n]);
        float e[NB], lse = 0.0f;
        #pragma unroll
        for (int n = 0; n < NB; n++) { e[n] = __expf(sc[n] - m1); lse += e[n]; }

        float loglse = logf(lse);
        float ent1 = 0.0f;
        #pragma unroll
        for (int n = 0; n < NB; n++) {
            float p  = e[n] / lse;
            float lp = (sc[n] - m1) - loglse;
            ent1 -= p * lp;
        }

        // ---- phase 2 merge
        float sp    = sc[NB];
        float mm    = fmaxf(m1, sp);
        float c1    = __expf(m1 - mm);
        float cp    = __expf(sp - mm);
        float denom = c1 * lse + cp;
        float pw1   = c1 * lse / denom;
        float pw2   = cp / denom;

        // ---- weighted sum from regs
        float4 h0 = make_float4(0.f, 0.f, 0.f, 0.f);
        float4 h1 = make_float4(0.f, 0.f, 0.f, 0.f);
        #pragma unroll
        for (int n = 0; n < NB; n++) {
            h0 = fma4(x[n][0], e[n], h0);
            h1 = fma4(x[n][1], e[n], h1);
        }
        h0.x = h0.x * pw1 + x[NB][0].x * pw2;
        h0.y = h0.y * pw1 + x[NB][0].y * pw2;
        h0.z = h0.z * pw1 + x[NB][0].z * pw2;
        h0.w = h0.w * pw1 + x[NB][0].w * pw2;
        h1.x = h1.x * pw1 + x[NB][1].x * pw2;
        h1.y = h1.y * pw1 + x[NB][1].y * pw2;
        h1.z = h1.z * pw1 + x[NB][1].z * pw2;
        h1.w = h1.w * pw1 + x[NB][1].w * pw2;

        float4* o4 = reinterpret_cast<float4*>(out + (size_t)bt * DD);
        o4[tid]           = h0;
        o4[tid + THREADS] = h1;

        if (tid == 0) {
            float w1c = fmaxf(pw1, 1e-8f);
            float w2c = fmaxf(pw2, 1e-8f);
            ent_out[bt] = w1c * ent1 - w1c * logf(w1c) - w2c * logf(w2c);
        }
        if (tid < NB)  w_out[(size_t)bt * 9 + tid] = (e[tid] / lse) * pw1;
        if (tid == NB) w_out[(size_t)bt * 9 + NB]  = pw2;

        s++; if (s == NSTAGE) { s = 0; par ^= 1; }
    }
}

extern "C" void kernel_launch(void* const* d_in, const int* in_sizes, int n_in,
                              void* d_out, int out_size) {
    const float* cb  = (const float*)d_in[0];
    const float* pb  = (const float*)d_in[1];
    const float* wq  = (const float*)d_in[2];
    const float* knw = (const float*)d_in[3];
    float* out = (float*)d_out;

    int nsm = 148;
    cudaDeviceGetAttribute(&nsm, cudaDevAttrMultiProcessorCount, 0);
    if (nsm <= 0 || nsm > NTOK) nsm = 148;

    cudaFuncSetAttribute(reloop_tma_kernel,
                         cudaFuncAttributeMaxDynamicSharedMemorySize, SMEM_BYTES);
    reloop_tma_kernel<<<nsm, THREADS, SMEM_BYTES>>>(cb, pb, wq, knw, out);
}